// round 14
// baseline (speedup 1.0000x reference)
#include <cuda_runtime.h>
#include <math.h>

#define NRENDER 16        // NF(2) * T(8)
#define NFACE_C 1024
#define HW 128
#define TEXW 256
#define KSZ 11

// ---------------- device scratch ----------------
__device__ float4 g_plane4[NRENDER][NFACE_C][3]; // {A0,B0,C0,A1},{B1,C1,A2,B2},{C2,zA,zB,zC}
__device__ float4 g_bbox[NRENDER][NFACE_C];      // xmin,xmax,ymin,ymax (dense scan stream)
__device__ float  g_uvp[NRENDER][NFACE_C][8];    // uA,uB,uC,vA,vB,vC,pad,pad
__device__ float  g_img[NRENDER][4][HW][HW];     // rgb + raw mask

// 11-tap gaussian literals (sigma=1), center at index 5
#define GW0 1.4867195147e-06f
#define GW1 1.3383022576e-04f
#define GW2 4.4318484119e-03f
#define GW3 5.3990966513e-02f
#define GW4 2.4197072452e-01f
#define GW5 3.9894228040e-01f

__device__ __forceinline__ unsigned fkey(float f) {
    unsigned u = __float_as_uint(f);
    return u ^ ((u & 0x80000000u) ? 0xFFFFFFFFu : 0x80000000u);
}

// ---------------- quaternion helper ----------------
__device__ __forceinline__ void quat_to_R_dev(const float* q, float scale, float* R) {
    float c = q[0], x = q[1], y = q[2], z = q[3];
    float sin2 = x*x + y*y + z*z;
    float sint = sqrtf(fmaxf(sin2, 1e-12f));
    float tt = 2.0f * ((c < 0.0f) ? atan2f(-sint, -c) : atan2f(sint, c));
    float k = (sin2 > 1e-12f) ? (tt / sint) : 2.0f;
    float ax = k*x*scale, ay = k*y*scale, az = k*z*scale;
    float th = sqrtf(ax*ax + ay*ay + az*az);
    float inv = 1.0f / fmaxf(th, 1e-8f);
    float ux = ax*inv, uy = ay*inv, uz = az*inv;
    float s = sinf(th), co = cosf(th), oc = 1.0f - co;
    R[0] = 1.0f + oc*(-(uy*uy + uz*uz));
    R[1] = -s*uz + oc*(ux*uy);
    R[2] =  s*uy + oc*(ux*uz);
    R[3] =  s*uz + oc*(ux*uy);
    R[4] = 1.0f + oc*(-(ux*ux + uz*uz));
    R[5] = -s*ux + oc*(uy*uz);
    R[6] = -s*uy + oc*(ux*uz);
    R[7] =  s*ux + oc*(uy*uz);
    R[8] = 1.0f + oc*(-(ux*ux + uy*uy));
}

// ---------------- per (render, face) plane setup ----------------
// grid (4, NRENDER) = 64 blocks x 256 threads — ONE wave on 148 SMs.
// Thread 0 computes the rotation chain into shared; all threads' vertex/uv
// gathers are issued FIRST so their latency overlaps the serial chain.
__global__ void __launch_bounds__(256) face_kernel(
        const float* __restrict__ verts, const int* __restrict__ faces,
        const float* __restrict__ ff,
        const float* __restrict__ quat, const float* __restrict__ trans) {
    __shared__ float sRT[12];
    int r = blockIdx.y;
    int fc = blockIdx.x * 256 + threadIdx.x;

    // ---- issue all gathers first (independent of rotation chain) ----
    int vi0 = faces[fc*3 + 0], vi1 = faces[fc*3 + 1], vi2 = faces[fc*3 + 2];
    float V[3][3];
    V[0][0] = verts[vi0*3+0]; V[0][1] = verts[vi0*3+1]; V[0][2] = verts[vi0*3+2];
    V[1][0] = verts[vi1*3+0]; V[1][1] = verts[vi1*3+1]; V[1][2] = verts[vi1*3+2];
    V[2][0] = verts[vi2*3+0]; V[2][1] = verts[vi2*3+1]; V[2][2] = verts[vi2*3+2];
    float u0 = ff[fc*6+0], v0 = ff[fc*6+1];
    float u1 = ff[fc*6+2], v1 = ff[fc*6+3];
    float u2 = ff[fc*6+4], v2 = ff[fc*6+5];

    // ---- serial rotation chain: ONE thread per block ----
    if (threadIdx.x == 0) {
        int f = r >> 3, t = r & 7;
        float R0[9], Rs[9];
        quat_to_R_dev(&quat[f*8 + 4], 1.0f, R0);     // q[:,f,1]
        quat_to_R_dev(&quat[f*8 + 0], 0.125f, Rs);   // q[:,f,0]/T/ROT_DIV
        float Rm[9];
        #pragma unroll
        for (int k = 0; k < 9; k++) Rm[k] = R0[k];
        for (int s = 0; s < t; s++) {
            float Nw[9];
            #pragma unroll
            for (int i = 0; i < 3; i++)
                #pragma unroll
                for (int k = 0; k < 3; k++)
                    Nw[i*3+k] = Rm[i*3+0]*Rs[0*3+k] + Rm[i*3+1]*Rs[1*3+k] + Rm[i*3+2]*Rs[2*3+k];
            #pragma unroll
            for (int k = 0; k < 9; k++) Rm[k] = Nw[k];
        }
        #pragma unroll
        for (int k = 0; k < 9; k++) sRT[k] = Rm[k];
        float ti = (float)t / 7.0f;
        #pragma unroll
        for (int a = 0; a < 3; a++)
            sRT[9+a] = trans[a*4 + f*2 + 1] + ti * trans[a*4 + f*2 + 0];
    }
    __syncthreads();
    float R[12];
    #pragma unroll
    for (int k = 0; k < 12; k++) R[k] = sRT[k];

    const float invt = 1.0f / tanf(0.3925f);   // 1/tan(FOV/2); px==py since W==H
    float sx[3], sy[3], zz[3], P[3][3];
    #pragma unroll
    for (int k = 0; k < 3; k++) {
        float vx = V[k][0], vy = V[k][1], vz = V[k][2];
        float Xc = R[0]*vx + R[1]*vy + R[2]*vz + R[9];
        float Yc = R[3]*vx + R[4]*vy + R[5]*vz + R[10];
        float Zc = R[6]*vx + R[7]*vy + R[8]*vz + R[11] - 2.0f;   // CAM_D
        P[k][0] = Xc; P[k][1] = Yc; P[k][2] = Zc;
        float invnz = 1.0f / (-Zc);
        sx[k] = (Xc * invt) * invnz;
        sy[k] = (Yc * invt) * invnz;
        zz[k] = Zc;
    }
    float e1x = P[1][0]-P[0][0], e1y = P[1][1]-P[0][1], e1z = P[1][2]-P[0][2];
    float e2x = P[2][0]-P[0][0], e2y = P[2][1]-P[0][1], e2z = P[2][2]-P[0][2];
    float nx = e1y*e2z - e1z*e2y;
    float ny = e1z*e2x - e1x*e2z;
    float nzv = e1x*e2y - e1y*e2x;
    float nz = nzv / (sqrtf(nx*nx + ny*ny + nzv*nzv) + 1e-8f);

    float area = (sx[1]-sx[0])*(sy[2]-sy[0]) - (sy[1]-sy[0])*(sx[2]-sx[0]);
    if (fabsf(area) < 1e-10f) area = 1e-10f;
    float ia = 1.0f / area;
    float A0 = -(sy[2]-sy[1])*ia, B0 = (sx[2]-sx[1])*ia;
    float C0 = ((sy[2]-sy[1])*sx[1] - (sx[2]-sx[1])*sy[1])*ia;
    float A1 = -(sy[0]-sy[2])*ia, B1 = (sx[0]-sx[2])*ia;
    float C1 = ((sy[0]-sy[2])*sx[2] - (sx[0]-sx[2])*sy[2])*ia;
    float A2 = -(sy[1]-sy[0])*ia, B2 = (sx[1]-sx[0])*ia;
    float C2 = ((sy[1]-sy[0])*sx[0] - (sx[1]-sx[0])*sy[0])*ia;
    float zA = A0*zz[0] + A1*zz[1] + A2*zz[2];
    float zB = B0*zz[0] + B1*zz[1] + B2*zz[2];
    float zC = C0*zz[0] + C1*zz[1] + C2*zz[2];

    float xmin, xmax, ymin, ymax;
    if (nz > 0.0f) {
        xmin = fminf(sx[0], fminf(sx[1], sx[2]));
        xmax = fmaxf(sx[0], fmaxf(sx[1], sx[2]));
        ymin = fminf(sy[0], fminf(sy[1], sy[2]));
        ymax = fmaxf(sy[0], fmaxf(sy[1], sy[2]));
    } else {
        xmin = 1e30f; xmax = -1e30f; ymin = 1e30f; ymax = -1e30f;  // never passes cull
    }
    g_plane4[r][fc][0] = make_float4(A0, B0, C0, A1);
    g_plane4[r][fc][1] = make_float4(B1, C1, A2, B2);
    g_plane4[r][fc][2] = make_float4(C2, zA, zB, zC);
    g_bbox[r][fc]      = make_float4(xmin, xmax, ymin, ymax);

    float* up = g_uvp[r][fc];
    up[0] = A0*u0 + A1*u1 + A2*u2;
    up[1] = B0*u0 + B1*u1 + B2*u2;
    up[2] = C0*u0 + C1*u1 + C2*u2;
    up[3] = A0*v0 + A1*v1 + A2*v2;
    up[4] = B0*v0 + B1*v1 + B2*v2;
    up[5] = C0*v0 + C1*v1 + C2*v2;
}

// ---------------- rasterize + texture sample ----------------
// grid: (64 tiles, 16 renders), block 256 = 16x16 px (1 px/thread), 48KB dynamic.
// Dense-bbox compaction scan; block M cull + per-lane running depth cull.
__global__ void __launch_bounds__(256) raster_kernel(const float* __restrict__ tex) {
    extern __shared__ float sm[];         // 12288 floats = 48KB
    __shared__ unsigned s_key[NFACE_C];   // zmax keys: partial at [p], full at [1023-p]
    __shared__ int s_fid[NFACE_C];        // face ids, same layout
    __shared__ int s_np, s_nf;
    __shared__ unsigned s_M;
    int r = blockIdx.y;
    int tile = blockIdx.x;
    int tx = tile & 7, ty = tile >> 3;
    int lj = threadIdx.x & 15, li = threadIdx.x >> 4;
    int j = tx*16 + lj, i = ty*16 + li;
    const float step = 2.0f / 127.0f;
    float X = -1.0f + (float)j * step;
    float Y =  1.0f - (float)i * step;
    float tX0 = -1.0f + (float)(tx*16) * step;
    float tX1 = -1.0f + (float)(tx*16 + 15) * step;
    float tY0 =  1.0f - (float)(ty*16) * step;
    float tY1 =  1.0f - (float)(ty*16 + 15) * step;

    if (threadIdx.x == 0) { s_np = 0; s_nf = 0; s_M = 0u; }
    __syncthreads();

    for (int fc = threadIdx.x; fc < NFACE_C; fc += 256) {
        float4 bb = g_bbox[r][fc];
        if (!(bb.x <= tX1 && bb.y >= tX0 && bb.z <= tY0 && bb.w >= tY1)) continue;
        float4 a = g_plane4[r][fc][0];
        float4 b = g_plane4[r][fc][1];
        float4 c = g_plane4[r][fc][2];
        bool reject = false, full = true;
        {
            float A[3] = {a.x, a.w, b.z}, Bc[3] = {a.y, b.x, b.w}, Cc[3] = {a.z, b.y, c.x};
            #pragma unroll
            for (int e = 0; e < 3; e++) {
                float e00 = fmaf(A[e], tX0, fmaf(Bc[e], tY0, Cc[e]));
                float e01 = fmaf(A[e], tX1, fmaf(Bc[e], tY0, Cc[e]));
                float e10 = fmaf(A[e], tX0, fmaf(Bc[e], tY1, Cc[e]));
                float e11 = fmaf(A[e], tX1, fmaf(Bc[e], tY1, Cc[e]));
                float mn = fminf(fminf(e00, e01), fminf(e10, e11));
                float mx = fmaxf(fmaxf(e00, e01), fmaxf(e10, e11));
                if (mx < 0.0f) reject = true;
                if (mn < 0.0f) full = false;
            }
        }
        if (reject) continue;
        float z00 = fmaf(c.y, tX0, fmaf(c.z, tY0, c.w));
        float z01 = fmaf(c.y, tX1, fmaf(c.z, tY0, c.w));
        float z10 = fmaf(c.y, tX0, fmaf(c.z, tY1, c.w));
        float z11 = fmaf(c.y, tX1, fmaf(c.z, tY1, c.w));
        float zmx = fmaxf(fmaxf(z00, z01), fmaxf(z10, z11));
        if (full) {
            float zmn = fminf(fminf(z00, z01), fminf(z10, z11));
            atomicMax(&s_M, fkey(zmn - 1e-6f));
            int p = atomicAdd(&s_nf, 1);
            float* d = sm + 12288 - 4*(p+1);
            d[0] = c.y; d[1] = c.z; d[2] = c.w;
            s_fid[1023 - p] = fc;
            s_key[1023 - p] = fkey(zmx);
        } else {
            int p = atomicAdd(&s_np, 1);
            float* d = sm + p*12;
            *(float4*)(d + 0) = a;
            *(float4*)(d + 4) = b;
            *(float4*)(d + 8) = c;
            s_fid[p] = fc;
            s_key[p] = fkey(zmx);
        }
    }
    __syncthreads();
    int np = s_np, nf = s_nf;
    unsigned M = s_M;

    float    best_z  = -3.0e38f;
    int      best_f  = 0x7fffffff;
    unsigned bestkey = 0u;
    int      hit_i   = (nf > 0) ? 1 : 0;

    for (int q = 0; q < nf; q++) {
        unsigned key = s_key[1023 - q];
        if (key < M || key < bestkey) continue;
        const float4 zr = *(const float4*)(sm + 12288 - 4*(q+1));
        float z = fmaf(zr.x, X, fmaf(zr.y, Y, zr.z));
        int fid = s_fid[1023 - q];
        if (z > best_z) { best_z = z; best_f = fid; bestkey = fkey(z); }
        else if (z == best_z && fid < best_f) { best_f = fid; }
    }
    for (int q = 0; q < np; q++) {
        if (s_key[q] < bestkey) continue;
        const float* d = sm + q*12;
        float4 a = *(const float4*)(d + 0);
        float4 b = *(const float4*)(d + 4);
        float4 c = *(const float4*)(d + 8);
        int fid = s_fid[q];
        float b0 = fmaf(a.x, X, fmaf(a.y, Y, a.z));
        float b1 = fmaf(a.w, X, fmaf(b.x, Y, b.y));
        float b2 = fmaf(b.z, X, fmaf(b.w, Y, c.x));
        float z  = fmaf(c.y, X, fmaf(c.z, Y, c.w));
        if (fminf(b0, fminf(b1, b2)) >= 0.0f) {
            hit_i = 1;
            if (z > best_z) { best_z = z; best_f = fid; bestkey = fkey(z); }
            else if (z == best_z && fid < best_f) { best_f = fid; }
        }
    }

    float u = 0.0f, v = 0.0f;
    if (hit_i) {
        const float* up = g_uvp[r][best_f];
        u = fmaf(up[0], X, fmaf(up[1], Y, up[2]));
        v = fmaf(up[3], X, fmaf(up[4], Y, up[5]));
    }
    float xf = u * 255.0f;
    float yf = (1.0f - v) * 255.0f;
    float x0 = fminf(fmaxf(floorf(xf), 0.0f), 254.0f);
    float y0 = fminf(fmaxf(floorf(yf), 0.0f), 254.0f);
    float fx = xf - x0, fy = yf - y0;
    int xi = (int)x0, yi = (int)y0;
    int base = yi * TEXW + xi;
    #pragma unroll
    for (int cch = 0; cch < 3; cch++) {
        const float* tc = tex + cch * (TEXW*TEXW);
        float t00 = __ldg(tc + base);
        float t01 = __ldg(tc + base + 1);
        float t10 = __ldg(tc + base + TEXW);
        float t11 = __ldg(tc + base + TEXW + 1);
        float val = t00*(1.0f-fx)*(1.0f-fy) + t01*fx*(1.0f-fy)
                  + t10*(1.0f-fx)*fy        + t11*fx*fy;
        g_img[r][cch][i][j] = val;
    }
    g_img[r][3][i][j] = (float)hit_i;
}

// ---------------- tiled fused epilogue ----------------
// grid (16 tiles, NRENDER, 4), block 256 as 32x8.
// z=0 -> MASK (launched FIRST); z=1..3 -> RGB.
// Mask: erode + ONE 21-tap pass per axis; border rows use clip-corrected
// weights computed per-block into shared (s_w21).
__global__ void __launch_bounds__(256) post_kernel(float* __restrict__ out) {
    extern __shared__ float sm[];
    __shared__ float s_w21[11][21];
    const float GW[KSZ] = {GW0,GW1,GW2,GW3,GW4,GW5,GW4,GW3,GW2,GW1,GW0};
    const float W21[21] = {
        2.2103349e-12f, 3.9795740e-10f, 3.1088500e-08f, 1.3467706e-06f,
        3.4812100e-05f, 5.4450606e-04f, 5.1673262e-03f, 2.9729460e-02f,
        1.0378766e-01f, 2.1967292e-01f, 2.8212397e-01f, 2.1967292e-01f,
        1.0378766e-01f, 2.9729460e-02f, 5.1673262e-03f, 5.4450606e-04f,
        3.4812100e-05f, 1.3467706e-06f, 3.1088500e-08f, 3.9795740e-10f,
        2.2103349e-12f };
    int tile = blockIdx.x, r = blockIdx.y;
    int c = (blockIdx.z + 3) & 3;           // z=0 -> c=3 (mask first)
    int tx = tile & 3, ty = tile >> 2;      // 4x4 tiles of 32x32
    int lx = threadIdx.x & 31, ly = threadIdx.x >> 5;   // 32x8

    if (c < 3) {
        // ---- RGB: 43x42 padded halo-5 load, vblur(window) -> 32x42, hblur -> 32x32 ----
        float* bufIn  = sm;                  // 43*42 (row 42 = scratch pad)
        float* bufMid = sm + 43*42;          // 32 rows x 42 cols
        const int gy0 = ty*32 - 5, gx0 = tx*32 - 5;
        for (int li = ly; li < 42; li += 8) {
            int gi = gy0 + li;
            bool rowok = (gi >= 0 && gi < HW);
            {   int lj = lx;       int gj = gx0 + lj;
                bufIn[li*42 + lj] = (rowok && gj >= 0 && gj < HW) ? g_img[r][c][gi][gj] : 0.0f; }
            if (lx < 10) { int lj = lx + 32; int gj = gx0 + lj;
                bufIn[li*42 + lj] = (rowok && gj >= 0 && gj < HW) ? g_img[r][c][gi][gj] : 0.0f; }
        }
        __syncthreads();
        {
            int r0 = ly * 4;
            #pragma unroll
            for (int cb = 0; cb < 2; cb++) {
                int lj = lx + cb*32;
                if (cb == 0 || lx < 10) {
                    float w[KSZ];
                    #pragma unroll
                    for (int k = 0; k < KSZ; k++) w[k] = bufIn[(r0 + k)*42 + lj];
                    #pragma unroll
                    for (int o = 0; o < 4; o++) {
                        float acc = 0.0f;
                        #pragma unroll
                        for (int k = 0; k < KSZ; k++) acc = fmaf(GW[k], w[k], acc);
                        bufMid[(r0 + o)*42 + lj] = acc;
                        #pragma unroll
                        for (int k = 0; k < KSZ-1; k++) w[k] = w[k+1];
                        w[KSZ-1] = bufIn[(r0 + o + KSZ)*42 + lj];
                    }
                }
            }
        }
        __syncthreads();
        for (int li = ly; li < 32; li += 8) {
            float acc = 0.0f;
            #pragma unroll
            for (int k = 0; k < KSZ; k++) acc = fmaf(GW[k], bufMid[li*42 + lx + k], acc);
            out[((r*4 + c) << 14) + (ty*32 + li)*HW + tx*32 + lx] = acc;
        }
        return;
    }

    // ---- MASK: 74x74 halo-21, erode + one 21-tap V pass + one 21-tap H pass ----
    float* bufA = sm;            // 74*74 = 5476
    float* bufB = sm + 5476;
    const int gy0 = ty*32 - 21, gx0 = tx*32 - 21;
    if (threadIdx.x < 231) {
        int b = threadIdx.x / 21, t = threadIdx.x % 21;
        int jj = b + t - 10;
        float w = 0.0f;
        if (jj >= 0) {
            int kmin = max(0, max(b-5, jj-5));
            int kmax = min(b+5, jj+5);
            for (int k = kmin; k <= kmax; k++)
                w += GW[k-b+5] * GW[jj-k+5];
        }
        s_w21[b][t] = w;
    }
    for (int li = ly; li < 74; li += 8) {
        int gi = gy0 + li;
        bool rowok = (gi >= 0 && gi < HW);
        #pragma unroll
        for (int cb = 0; cb < 3; cb++) {
            int lj = lx + cb*32;
            if (lj < 74) {
                int gj = gx0 + lj;
                bufA[li*74 + lj] = (rowok && gj >= 0 && gj < HW) ? g_img[r][3][gi][gj] : 3.0e38f;
            }
        }
    }
    __syncthreads();
    for (int li = 10 + ly; li < 64; li += 8) {
        int gi = gy0 + li;
        #pragma unroll
        for (int cb = 0; cb < 2; cb++) {
            int lj = 10 + lx + cb*32;
            if (lj < 64) {
                int gj = gx0 + lj;
                const float* rm = bufA + (li-1)*74 + lj;
                const float* r0 = bufA + li*74 + lj;
                const float* rp = bufA + (li+1)*74 + lj;
                float m = fminf(fminf(fminf(rm[-1], rm[0]), fminf(rm[1], r0[-1])),
                                fminf(fminf(r0[0], r0[1]), fminf(fminf(rp[-1], rp[0]), rp[1])));
                bool inimg = (gi >= 0 && gi < HW && gj >= 0 && gj < HW);
                bufB[li*74 + lj] = inimg ? m : 0.0f;
            }
        }
    }
    __syncthreads();
    for (int li = 21 + ly; li < 53; li += 8) {
        int gi = gy0 + li;
        int bi = min(min(gi, 127 - gi), 10);
        #pragma unroll
        for (int cb = 0; cb < 2; cb++) {
            int lj = 10 + lx + cb*32;
            if (lj < 64) {
                float acc = 0.0f;
                if (bi == 10) {
                    #pragma unroll
                    for (int t = 0; t < 21; t++)
                        acc = fmaf(W21[t], bufB[(li + t - 10)*74 + lj], acc);
                } else {
                    bool flip = (gi > 63);
                    const float* wr = s_w21[bi];
                    #pragma unroll
                    for (int t = 0; t < 21; t++)
                        acc = fmaf(wr[flip ? 20 - t : t],
                                   bufB[(li + t - 10)*74 + lj], acc);
                }
                bufA[li*74 + lj] = acc;
            }
        }
    }
    __syncthreads();
    for (int li = 21 + ly; li < 53; li += 8) {
        int lj = 21 + lx;
        int gj = gx0 + lj;
        int bj = min(min(gj, 127 - gj), 10);
        float acc = 0.0f;
        if (bj == 10) {
            #pragma unroll
            for (int t = 0; t < 21; t++)
                acc = fmaf(W21[t], bufA[li*74 + lj + t - 10], acc);
        } else {
            bool flip = (gj > 63);
            const float* wr = s_w21[bj];
            #pragma unroll
            for (int t = 0; t < 21; t++)
                acc = fmaf(wr[flip ? 20 - t : t],
                           bufA[li*74 + lj + t - 10], acc);
        }
        out[((r*4 + 3) << 14) + (gy0 + li)*HW + gj] = acc;
    }
}

// ---------------- launcher ----------------
extern "C" void kernel_launch(void* const* d_in, const int* in_sizes, int n_in,
                              void* d_out, int out_size) {
    const float* vertices  = (const float*)d_in[0];
    const float* quat      = (const float*)d_in[1];
    const float* trans     = (const float*)d_in[2];
    const float* face_ff   = (const float*)d_in[4];
    const float* tex       = (const float*)d_in[5];
    const int*   faces     = (const int*)d_in[6];
    float* out = (float*)d_out;

    static bool attr_set = false;
    if (!attr_set) {
        cudaFuncSetAttribute(raster_kernel, cudaFuncAttributeMaxDynamicSharedMemorySize, 49152);
        cudaFuncSetAttribute(post_kernel,   cudaFuncAttributeMaxDynamicSharedMemorySize, 45056);
        attr_set = true;
    }

    face_kernel<<<dim3(4, NRENDER), 256>>>(vertices, faces, face_ff, quat, trans);
    raster_kernel<<<dim3(64, NRENDER), 256, 49152>>>(tex);
    post_kernel<<<dim3(16, NRENDER, 4), 256, 45056>>>(out);
}

// round 15
// speedup vs baseline: 1.0430x; 1.0430x over previous
#include <cuda_runtime.h>
#include <math.h>

#define NRENDER 16        // NF(2) * T(8)
#define NFACE_C 1024
#define HW 128
#define TEXW 256
#define KSZ 11

// ---------------- device scratch ----------------
__device__ float4 g_plane4[NRENDER][NFACE_C][3]; // {A0,B0,C0,A1},{B1,C1,A2,B2},{C2,zA,zB,zC}
__device__ float4 g_bbox[NRENDER][NFACE_C];      // xmin,xmax,ymin,ymax (dense scan stream)
__device__ float  g_uvp[NRENDER][NFACE_C][8];    // uA,uB,uC,vA,vB,vC,pad,pad
__device__ float  g_img[NRENDER][4][HW][HW];     // rgb + raw mask

// 11-tap gaussian literals (sigma=1), center at index 5
#define GW0 1.4867195147e-06f
#define GW1 1.3383022576e-04f
#define GW2 4.4318484119e-03f
#define GW3 5.3990966513e-02f
#define GW4 2.4197072452e-01f
#define GW5 3.9894228040e-01f

__device__ __forceinline__ unsigned fkey(float f) {
    unsigned u = __float_as_uint(f);
    return u ^ ((u & 0x80000000u) ? 0xFFFFFFFFu : 0x80000000u);
}

// ---------------- quaternion helper ----------------
__device__ __forceinline__ void quat_to_R_dev(const float* q, float scale, float* R) {
    float c = q[0], x = q[1], y = q[2], z = q[3];
    float sin2 = x*x + y*y + z*z;
    float sint = sqrtf(fmaxf(sin2, 1e-12f));
    float tt = 2.0f * ((c < 0.0f) ? atan2f(-sint, -c) : atan2f(sint, c));
    float k = (sin2 > 1e-12f) ? (tt / sint) : 2.0f;
    float ax = k*x*scale, ay = k*y*scale, az = k*z*scale;
    float th = sqrtf(ax*ax + ay*ay + az*az);
    float inv = 1.0f / fmaxf(th, 1e-8f);
    float ux = ax*inv, uy = ay*inv, uz = az*inv;
    float s = sinf(th), co = cosf(th), oc = 1.0f - co;
    R[0] = 1.0f + oc*(-(uy*uy + uz*uz));
    R[1] = -s*uz + oc*(ux*uy);
    R[2] =  s*uy + oc*(ux*uz);
    R[3] =  s*uz + oc*(ux*uy);
    R[4] = 1.0f + oc*(-(ux*ux + uz*uz));
    R[5] = -s*ux + oc*(uy*uz);
    R[6] = -s*uy + oc*(ux*uz);
    R[7] =  s*ux + oc*(uy*uz);
    R[8] = 1.0f + oc*(-(ux*ux + uy*uy));
}

// ---------------- per (render, face) plane setup (round-12 config, frozen) ----------------
// grid (16, NRENDER), block 64; per-thread rotation chain; gathers hoisted.
__global__ void __launch_bounds__(64) face_kernel(
        const float* __restrict__ verts, const int* __restrict__ faces,
        const float* __restrict__ ff,
        const float* __restrict__ quat, const float* __restrict__ trans) {
    int r = blockIdx.y;
    int fc = blockIdx.x * 64 + threadIdx.x;
    int f = r >> 3, t = r & 7;

    // ---- issue all gathers first (independent of rotation chain) ----
    int vi0 = faces[fc*3 + 0], vi1 = faces[fc*3 + 1], vi2 = faces[fc*3 + 2];
    float V[3][3];
    V[0][0] = verts[vi0*3+0]; V[0][1] = verts[vi0*3+1]; V[0][2] = verts[vi0*3+2];
    V[1][0] = verts[vi1*3+0]; V[1][1] = verts[vi1*3+1]; V[1][2] = verts[vi1*3+2];
    V[2][0] = verts[vi2*3+0]; V[2][1] = verts[vi2*3+1]; V[2][2] = verts[vi2*3+2];
    float u0 = ff[fc*6+0], v0 = ff[fc*6+1];
    float u1 = ff[fc*6+2], v1 = ff[fc*6+3];
    float u2 = ff[fc*6+4], v2 = ff[fc*6+5];

    // ---- serial rotation chain (overlaps the loads above) ----
    float R[12];
    {
        float R0[9], Rs[9];
        quat_to_R_dev(&quat[f*8 + 4], 1.0f, R0);     // q[:,f,1]
        quat_to_R_dev(&quat[f*8 + 0], 0.125f, Rs);   // q[:,f,0]/T/ROT_DIV
        float Rm[9];
        #pragma unroll
        for (int k = 0; k < 9; k++) Rm[k] = R0[k];
        for (int s = 0; s < t; s++) {
            float Nw[9];
            #pragma unroll
            for (int i = 0; i < 3; i++)
                #pragma unroll
                for (int k = 0; k < 3; k++)
                    Nw[i*3+k] = Rm[i*3+0]*Rs[0*3+k] + Rm[i*3+1]*Rs[1*3+k] + Rm[i*3+2]*Rs[2*3+k];
            #pragma unroll
            for (int k = 0; k < 9; k++) Rm[k] = Nw[k];
        }
        #pragma unroll
        for (int k = 0; k < 9; k++) R[k] = Rm[k];
        float ti = (float)t / 7.0f;
        #pragma unroll
        for (int a = 0; a < 3; a++)
            R[9+a] = trans[a*4 + f*2 + 1] + ti * trans[a*4 + f*2 + 0];
    }

    const float invt = 1.0f / tanf(0.3925f);   // 1/tan(FOV/2); px==py since W==H
    float sx[3], sy[3], zz[3], P[3][3];
    #pragma unroll
    for (int k = 0; k < 3; k++) {
        float vx = V[k][0], vy = V[k][1], vz = V[k][2];
        float Xc = R[0]*vx + R[1]*vy + R[2]*vz + R[9];
        float Yc = R[3]*vx + R[4]*vy + R[5]*vz + R[10];
        float Zc = R[6]*vx + R[7]*vy + R[8]*vz + R[11] - 2.0f;   // CAM_D
        P[k][0] = Xc; P[k][1] = Yc; P[k][2] = Zc;
        float invnz = 1.0f / (-Zc);
        sx[k] = (Xc * invt) * invnz;
        sy[k] = (Yc * invt) * invnz;
        zz[k] = Zc;
    }
    float e1x = P[1][0]-P[0][0], e1y = P[1][1]-P[0][1], e1z = P[1][2]-P[0][2];
    float e2x = P[2][0]-P[0][0], e2y = P[2][1]-P[0][1], e2z = P[2][2]-P[0][2];
    float nx = e1y*e2z - e1z*e2y;
    float ny = e1z*e2x - e1x*e2z;
    float nzv = e1x*e2y - e1y*e2x;
    float nz = nzv / (sqrtf(nx*nx + ny*ny + nzv*nzv) + 1e-8f);

    float area = (sx[1]-sx[0])*(sy[2]-sy[0]) - (sy[1]-sy[0])*(sx[2]-sx[0]);
    if (fabsf(area) < 1e-10f) area = 1e-10f;
    float ia = 1.0f / area;
    float A0 = -(sy[2]-sy[1])*ia, B0 = (sx[2]-sx[1])*ia;
    float C0 = ((sy[2]-sy[1])*sx[1] - (sx[2]-sx[1])*sy[1])*ia;
    float A1 = -(sy[0]-sy[2])*ia, B1 = (sx[0]-sx[2])*ia;
    float C1 = ((sy[0]-sy[2])*sx[2] - (sx[0]-sx[2])*sy[2])*ia;
    float A2 = -(sy[1]-sy[0])*ia, B2 = (sx[1]-sx[0])*ia;
    float C2 = ((sy[1]-sy[0])*sx[0] - (sx[1]-sx[0])*sy[0])*ia;
    float zA = A0*zz[0] + A1*zz[1] + A2*zz[2];
    float zB = B0*zz[0] + B1*zz[1] + B2*zz[2];
    float zC = C0*zz[0] + C1*zz[1] + C2*zz[2];

    float xmin, xmax, ymin, ymax;
    if (nz > 0.0f) {
        xmin = fminf(sx[0], fminf(sx[1], sx[2]));
        xmax = fmaxf(sx[0], fmaxf(sx[1], sx[2]));
        ymin = fminf(sy[0], fminf(sy[1], sy[2]));
        ymax = fmaxf(sy[0], fmaxf(sy[1], sy[2]));
    } else {
        xmin = 1e30f; xmax = -1e30f; ymin = 1e30f; ymax = -1e30f;  // never passes cull
    }
    g_plane4[r][fc][0] = make_float4(A0, B0, C0, A1);
    g_plane4[r][fc][1] = make_float4(B1, C1, A2, B2);
    g_plane4[r][fc][2] = make_float4(C2, zA, zB, zC);
    g_bbox[r][fc]      = make_float4(xmin, xmax, ymin, ymax);

    float* up = g_uvp[r][fc];
    up[0] = A0*u0 + A1*u1 + A2*u2;
    up[1] = B0*u0 + B1*u1 + B2*u2;
    up[2] = C0*u0 + C1*u1 + C2*u2;
    up[3] = A0*v0 + A1*v1 + A2*v2;
    up[4] = B0*v0 + B1*v1 + B2*v2;
    up[5] = C0*v0 + C1*v1 + C2*v2;
}

// ---------------- rasterize + texture sample (frozen, round-11/12) ----------------
// grid: (64 tiles, 16 renders), block 256 = 16x16 px (1 px/thread), 48KB dynamic.
__global__ void __launch_bounds__(256) raster_kernel(const float* __restrict__ tex) {
    extern __shared__ float sm[];         // 12288 floats = 48KB
    __shared__ unsigned s_key[NFACE_C];
    __shared__ int s_fid[NFACE_C];
    __shared__ int s_np, s_nf;
    __shared__ unsigned s_M;
    int r = blockIdx.y;
    int tile = blockIdx.x;
    int tx = tile & 7, ty = tile >> 3;
    int lj = threadIdx.x & 15, li = threadIdx.x >> 4;
    int j = tx*16 + lj, i = ty*16 + li;
    const float step = 2.0f / 127.0f;
    float X = -1.0f + (float)j * step;
    float Y =  1.0f - (float)i * step;
    float tX0 = -1.0f + (float)(tx*16) * step;
    float tX1 = -1.0f + (float)(tx*16 + 15) * step;
    float tY0 =  1.0f - (float)(ty*16) * step;
    float tY1 =  1.0f - (float)(ty*16 + 15) * step;

    if (threadIdx.x == 0) { s_np = 0; s_nf = 0; s_M = 0u; }
    __syncthreads();

    for (int fc = threadIdx.x; fc < NFACE_C; fc += 256) {
        float4 bb = g_bbox[r][fc];
        if (!(bb.x <= tX1 && bb.y >= tX0 && bb.z <= tY0 && bb.w >= tY1)) continue;
        float4 a = g_plane4[r][fc][0];
        float4 b = g_plane4[r][fc][1];
        float4 c = g_plane4[r][fc][2];
        bool reject = false, full = true;
        {
            float A[3] = {a.x, a.w, b.z}, Bc[3] = {a.y, b.x, b.w}, Cc[3] = {a.z, b.y, c.x};
            #pragma unroll
            for (int e = 0; e < 3; e++) {
                float e00 = fmaf(A[e], tX0, fmaf(Bc[e], tY0, Cc[e]));
                float e01 = fmaf(A[e], tX1, fmaf(Bc[e], tY0, Cc[e]));
                float e10 = fmaf(A[e], tX0, fmaf(Bc[e], tY1, Cc[e]));
                float e11 = fmaf(A[e], tX1, fmaf(Bc[e], tY1, Cc[e]));
                float mn = fminf(fminf(e00, e01), fminf(e10, e11));
                float mx = fmaxf(fmaxf(e00, e01), fmaxf(e10, e11));
                if (mx < 0.0f) reject = true;
                if (mn < 0.0f) full = false;
            }
        }
        if (reject) continue;
        float z00 = fmaf(c.y, tX0, fmaf(c.z, tY0, c.w));
        float z01 = fmaf(c.y, tX1, fmaf(c.z, tY0, c.w));
        float z10 = fmaf(c.y, tX0, fmaf(c.z, tY1, c.w));
        float z11 = fmaf(c.y, tX1, fmaf(c.z, tY1, c.w));
        float zmx = fmaxf(fmaxf(z00, z01), fmaxf(z10, z11));
        if (full) {
            float zmn = fminf(fminf(z00, z01), fminf(z10, z11));
            atomicMax(&s_M, fkey(zmn - 1e-6f));
            int p = atomicAdd(&s_nf, 1);
            float* d = sm + 12288 - 4*(p+1);
            d[0] = c.y; d[1] = c.z; d[2] = c.w;
            s_fid[1023 - p] = fc;
            s_key[1023 - p] = fkey(zmx);
        } else {
            int p = atomicAdd(&s_np, 1);
            float* d = sm + p*12;
            *(float4*)(d + 0) = a;
            *(float4*)(d + 4) = b;
            *(float4*)(d + 8) = c;
            s_fid[p] = fc;
            s_key[p] = fkey(zmx);
        }
    }
    __syncthreads();
    int np = s_np, nf = s_nf;
    unsigned M = s_M;

    float    best_z  = -3.0e38f;
    int      best_f  = 0x7fffffff;
    unsigned bestkey = 0u;
    int      hit_i   = (nf > 0) ? 1 : 0;

    for (int q = 0; q < nf; q++) {
        unsigned key = s_key[1023 - q];
        if (key < M || key < bestkey) continue;
        const float4 zr = *(const float4*)(sm + 12288 - 4*(q+1));
        float z = fmaf(zr.x, X, fmaf(zr.y, Y, zr.z));
        int fid = s_fid[1023 - q];
        if (z > best_z) { best_z = z; best_f = fid; bestkey = fkey(z); }
        else if (z == best_z && fid < best_f) { best_f = fid; }
    }
    for (int q = 0; q < np; q++) {
        if (s_key[q] < bestkey) continue;
        const float* d = sm + q*12;
        float4 a = *(const float4*)(d + 0);
        float4 b = *(const float4*)(d + 4);
        float4 c = *(const float4*)(d + 8);
        int fid = s_fid[q];
        float b0 = fmaf(a.x, X, fmaf(a.y, Y, a.z));
        float b1 = fmaf(a.w, X, fmaf(b.x, Y, b.y));
        float b2 = fmaf(b.z, X, fmaf(b.w, Y, c.x));
        float z  = fmaf(c.y, X, fmaf(c.z, Y, c.w));
        if (fminf(b0, fminf(b1, b2)) >= 0.0f) {
            hit_i = 1;
            if (z > best_z) { best_z = z; best_f = fid; bestkey = fkey(z); }
            else if (z == best_z && fid < best_f) { best_f = fid; }
        }
    }

    float u = 0.0f, v = 0.0f;
    if (hit_i) {
        const float* up = g_uvp[r][best_f];
        u = fmaf(up[0], X, fmaf(up[1], Y, up[2]));
        v = fmaf(up[3], X, fmaf(up[4], Y, up[5]));
    }
    float xf = u * 255.0f;
    float yf = (1.0f - v) * 255.0f;
    float x0 = fminf(fmaxf(floorf(xf), 0.0f), 254.0f);
    float y0 = fminf(fmaxf(floorf(yf), 0.0f), 254.0f);
    float fx = xf - x0, fy = yf - y0;
    int xi = (int)x0, yi = (int)y0;
    int base = yi * TEXW + xi;
    #pragma unroll
    for (int cch = 0; cch < 3; cch++) {
        const float* tc = tex + cch * (TEXW*TEXW);
        float t00 = __ldg(tc + base);
        float t01 = __ldg(tc + base + 1);
        float t10 = __ldg(tc + base + TEXW);
        float t11 = __ldg(tc + base + TEXW + 1);
        float val = t00*(1.0f-fx)*(1.0f-fy) + t01*fx*(1.0f-fy)
                  + t10*(1.0f-fx)*fy        + t11*fx*fy;
        g_img[r][cch][i][j] = val;
    }
    g_img[r][3][i][j] = (float)hit_i;
}

// ---------------- tiled fused epilogue, 64x32 tiles ----------------
// grid (8 tiles, NRENDER, 4), block 256 as 32x8. z=0 -> MASK (first).
// Mask: 106x74 halo-21 buffers; erode + one 21-tap V + one 21-tap H.
__global__ void __launch_bounds__(256) post_kernel(float* __restrict__ out) {
    extern __shared__ float sm[];
    __shared__ float s_w21[11][21];
    const float GW[KSZ] = {GW0,GW1,GW2,GW3,GW4,GW5,GW4,GW3,GW2,GW1,GW0};
    const float W21[21] = {
        2.2103349e-12f, 3.9795740e-10f, 3.1088500e-08f, 1.3467706e-06f,
        3.4812100e-05f, 5.4450606e-04f, 5.1673262e-03f, 2.9729460e-02f,
        1.0378766e-01f, 2.1967292e-01f, 2.8212397e-01f, 2.1967292e-01f,
        1.0378766e-01f, 2.9729460e-02f, 5.1673262e-03f, 5.4450606e-04f,
        3.4812100e-05f, 1.3467706e-06f, 3.1088500e-08f, 3.9795740e-10f,
        2.2103349e-12f };
    int tile = blockIdx.x, r = blockIdx.y;
    int c = (blockIdx.z + 3) & 3;           // z=0 -> c=3 (mask first)
    int tx = tile & 1, ty = tile >> 1;      // 2x4 tiles of 64x32
    int lx = threadIdx.x & 31, ly = threadIdx.x >> 5;   // 32x8

    if (c < 3) {
        // ---- RGB: 43x74 halo-5 load (row 42 pad), vblur window -> 32x74, hblur -> 32x64 ----
        float* bufIn  = sm;                  // 43*74
        float* bufMid = sm + 43*74;          // 32*74
        const int gy0 = ty*32 - 5, gx0 = tx*64 - 5;
        for (int li = ly; li < 42; li += 8) {
            int gi = gy0 + li;
            bool rowok = (gi >= 0 && gi < HW);
            #pragma unroll
            for (int cb = 0; cb < 3; cb++) {
                int lj = lx + cb*32;
                if (lj < 74) {
                    int gj = gx0 + lj;
                    bufIn[li*74 + lj] = (rowok && gj >= 0 && gj < HW) ? g_img[r][c][gi][gj] : 0.0f;
                }
            }
        }
        __syncthreads();
        {
            int r0 = ly * 4;
            #pragma unroll
            for (int cb = 0; cb < 3; cb++) {
                int lj = lx + cb*32;
                if (lj < 74) {
                    float w[KSZ];
                    #pragma unroll
                    for (int k = 0; k < KSZ; k++) w[k] = bufIn[(r0 + k)*74 + lj];
                    #pragma unroll
                    for (int o = 0; o < 4; o++) {
                        float acc = 0.0f;
                        #pragma unroll
                        for (int k = 0; k < KSZ; k++) acc = fmaf(GW[k], w[k], acc);
                        bufMid[(r0 + o)*74 + lj] = acc;
                        #pragma unroll
                        for (int k = 0; k < KSZ-1; k++) w[k] = w[k+1];
                        w[KSZ-1] = bufIn[(r0 + o + KSZ)*74 + lj];   // row <= 42 (pad)
                    }
                }
            }
        }
        __syncthreads();
        for (int li = ly; li < 32; li += 8) {
            #pragma unroll
            for (int cb = 0; cb < 2; cb++) {
                int ox = lx + cb*32;
                float acc = 0.0f;
                #pragma unroll
                for (int k = 0; k < KSZ; k++) acc = fmaf(GW[k], bufMid[li*74 + ox + k], acc);
                out[((r*4 + c) << 14) + (ty*32 + li)*HW + tx*64 + ox] = acc;
            }
        }
        return;
    }

    // ---- MASK: 106x74 halo-21, erode + one 21-tap V + one 21-tap H ----
    float* bufA = sm;            // 74 rows x 106 cols = 7844
    float* bufB = sm + 7844;
    const int gy0 = ty*32 - 21, gx0 = tx*64 - 21;
    if (threadIdx.x < 231) {
        int b = threadIdx.x / 21, t = threadIdx.x % 21;
        int jj = b + t - 10;
        float w = 0.0f;
        if (jj >= 0) {
            int kmin = max(0, max(b-5, jj-5));
            int kmax = min(b+5, jj+5);
            for (int k = kmin; k <= kmax; k++)
                w += GW[k-b+5] * GW[jj-k+5];
        }
        s_w21[b][t] = w;
    }
    // load raw mask, +INF outside image (erode input)
    for (int li = ly; li < 74; li += 8) {
        int gi = gy0 + li;
        bool rowok = (gi >= 0 && gi < HW);
        #pragma unroll
        for (int cb = 0; cb < 4; cb++) {
            int lj = lx + cb*32;
            if (lj < 106) {
                int gj = gx0 + lj;
                bufA[li*106 + lj] = (rowok && gj >= 0 && gj < HW) ? g_img[r][3][gi][gj] : 3.0e38f;
            }
        }
    }
    __syncthreads();
    // erode rows [10,64), cols [10,96): 3x3 min (INF pad); gate 0 outside image -> bufB
    for (int li = 10 + ly; li < 64; li += 8) {
        int gi = gy0 + li;
        #pragma unroll
        for (int cb = 0; cb < 3; cb++) {
            int lj = 10 + lx + cb*32;
            if (lj < 96) {
                int gj = gx0 + lj;
                const float* rm = bufA + (li-1)*106 + lj;
                const float* r0 = bufA + li*106 + lj;
                const float* rp = bufA + (li+1)*106 + lj;
                float m = fminf(fminf(fminf(rm[-1], rm[0]), fminf(rm[1], r0[-1])),
                                fminf(fminf(r0[0], r0[1]), fminf(fminf(rp[-1], rp[0]), rp[1])));
                bool inimg = (gi >= 0 && gi < HW && gj >= 0 && gj < HW);
                bufB[li*106 + lj] = inimg ? m : 0.0f;
            }
        }
    }
    __syncthreads();
    // V^2: 21-tap vertical, output rows [21,53), cols [10,96) -> bufA
    for (int li = 21 + ly; li < 53; li += 8) {
        int gi = gy0 + li;                       // in [0,128)
        int bi = min(min(gi, 127 - gi), 10);
        #pragma unroll
        for (int cb = 0; cb < 3; cb++) {
            int lj = 10 + lx + cb*32;
            if (lj < 96) {
                float acc = 0.0f;
                if (bi == 10) {
                    #pragma unroll
                    for (int t = 0; t < 21; t++)
                        acc = fmaf(W21[t], bufB[(li + t - 10)*106 + lj], acc);
                } else {
                    bool flip = (gi > 63);
                    const float* wr = s_w21[bi];
                    #pragma unroll
                    for (int t = 0; t < 21; t++)
                        acc = fmaf(wr[flip ? 20 - t : t],
                                   bufB[(li + t - 10)*106 + lj], acc);
                }
                bufA[li*106 + lj] = acc;
            }
        }
    }
    __syncthreads();
    // H^2: 21-tap horizontal, output rows [21,53), cols [21,85) -> out
    for (int li = 21 + ly; li < 53; li += 8) {
        #pragma unroll
        for (int cb = 0; cb < 2; cb++) {
            int lj = 21 + lx + cb*32;
            int gj = gx0 + lj;                   // in [0,128)
            int bj = min(min(gj, 127 - gj), 10);
            float acc = 0.0f;
            if (bj == 10) {
                #pragma unroll
                for (int t = 0; t < 21; t++)
                    acc = fmaf(W21[t], bufA[li*106 + lj + t - 10], acc);
            } else {
                bool flip = (gj > 63);
                const float* wr = s_w21[bj];
                #pragma unroll
                for (int t = 0; t < 21; t++)
                    acc = fmaf(wr[flip ? 20 - t : t],
                               bufA[li*106 + lj + t - 10], acc);
            }
            out[((r*4 + 3) << 14) + (gy0 + li)*HW + gj] = acc;
        }
    }
}

// ---------------- launcher ----------------
extern "C" void kernel_launch(void* const* d_in, const int* in_sizes, int n_in,
                              void* d_out, int out_size) {
    const float* vertices  = (const float*)d_in[0];
    const float* quat      = (const float*)d_in[1];
    const float* trans     = (const float*)d_in[2];
    const float* face_ff   = (const float*)d_in[4];
    const float* tex       = (const float*)d_in[5];
    const int*   faces     = (const int*)d_in[6];
    float* out = (float*)d_out;

    static bool attr_set = false;
    if (!attr_set) {
        cudaFuncSetAttribute(raster_kernel, cudaFuncAttributeMaxDynamicSharedMemorySize, 49152);
        cudaFuncSetAttribute(post_kernel,   cudaFuncAttributeMaxDynamicSharedMemorySize, 62752);
        attr_set = true;
    }

    face_kernel<<<dim3(16, NRENDER), 64>>>(vertices, faces, face_ff, quat, trans);
    raster_kernel<<<dim3(64, NRENDER), 256, 49152>>>(tex);
    post_kernel<<<dim3(8, NRENDER, 4), 256, 62752>>>(out);
}